// round 4
// baseline (speedup 1.0000x reference)
#include <cuda_runtime.h>
#include <cuda_bf16.h>
#include <math.h>

// Problem constants (fixed by the dataset)
#define MAX_VISITS   510
#define B_CAP        128
#define TOTAL_VISITS_CAP 38400
#define D_DIM        256
#define D_VEC        (D_DIM / 4)   // 64 float4 per row
#define MAX_DAYS_M1  364.0f
#define ROWS_PER_ITER 4            // 256-thread block, 64 threads per row

// Scratch (allocation-free rule: __device__ globals).
// Zero-initialized at module load. slot_map encodes v+1; 0 = pad row.
// Pad entries are never written (constant 0); visit entries are rewritten
// with identical values every call, so work/output are call-invariant.
__device__ int g_slot_map[B_CAP * MAX_VISITS];
__device__ int g_seg_start[TOTAL_VISITS_CAP];
__device__ int g_seg_end[TOTAL_VISITS_CAP];

// One thread handles 4 consecutive code_to_visit entries (int4) and detects
// segment boundaries; every visit has >=1 code so both bounds are always
// fully rewritten each call. Also scatters the visit->row map.
__global__ void vt_build_kernel(const int* __restrict__ code_to_visit,
                                const int* __restrict__ visit_person,
                                const int* __restrict__ visit_slot,
                                int total_codes, int total_visits) {
    int i = blockIdx.x * blockDim.x + threadIdx.x;
    int base = i * 4;
    if (base + 4 <= total_codes) {
        int4 c = *reinterpret_cast<const int4*>(code_to_visit + base);
        if (base == 0) g_seg_start[c.x] = 0;
        if (c.x != c.y) { g_seg_end[c.x] = base + 1; g_seg_start[c.y] = base + 1; }
        if (c.y != c.z) { g_seg_end[c.y] = base + 2; g_seg_start[c.z] = base + 2; }
        if (c.z != c.w) { g_seg_end[c.z] = base + 3; g_seg_start[c.w] = base + 3; }
        if (base + 4 == total_codes) {
            g_seg_end[c.w] = total_codes;
        } else {
            int nxt = code_to_visit[base + 4];
            if (c.w != nxt) { g_seg_end[c.w] = base + 4; g_seg_start[nxt] = base + 4; }
        }
    } else if (base < total_codes) {
        for (int k = base; k < total_codes; ++k) {
            int v = code_to_visit[k];
            if (k == 0 || code_to_visit[k - 1] != v) g_seg_start[v] = k;
            if (k == total_codes - 1 || code_to_visit[k + 1] != v) g_seg_end[v] = k + 1;
        }
    }
    if (i < total_visits) {
        g_slot_map[visit_person[i] * MAX_VISITS + visit_slot[i]] = i + 1;
    }
}

// Persistent main kernel. Each 256-thread block processes 4 rows per
// iteration of a grid-stride loop; within a row, 64 threads each own one
// float4 (4 consecutive dims). D/2 = 128 boundary is float4-aligned:
// t < 32 -> sin half, t >= 32 -> cos half.
// Fixed predicated unroll-16 gather keeps 16 independent float4 loads in
// flight per thread (MLP=16) -- this structure measured at ~98% of the
// LTS throughput cap in R2.
__global__ __launch_bounds__(64 * ROWS_PER_ITER, 4) void vt_main_kernel(
    const int* __restrict__ all_codes,
    const float* __restrict__ times,
    const float* __restrict__ concept_emb,
    const float* __restrict__ pad_embedding,
    const float* __restrict__ timescales,
    float* __restrict__ out,
    int n_rows) {
    int tid = threadIdx.x;            // 0..255
    int sub = tid >> 6;               // row group within block: 0..3
    int t   = tid & 63;               // lane within row: 0..63
    float4* out4 = reinterpret_cast<float4*>(out);
    const float4* emb4 = reinterpret_cast<const float4*>(concept_emb);

    int row_stride = gridDim.x * ROWS_PER_ITER;

    for (int row = blockIdx.x * ROWS_PER_ITER + sub; row < n_rows;
         row += row_stride) {
        int ve = g_slot_map[row];
        if (ve == 0) {
            float4 p = __ldg(reinterpret_cast<const float4*>(pad_embedding) + t);
            out4[(size_t)row * D_VEC + t] = p;
            continue;
        }
        int v = ve - 1;

        int start = g_seg_start[v];
        int end   = g_seg_end[v];

        float4 acc = make_float4(0.f, 0.f, 0.f, 0.f);

        // <=16 codes per visit; fully unrolled predicated loop keeps all
        // index loads and data loads independent -> deep MLP into L2.
        #pragma unroll
        for (int j = 0; j < 16; ++j) {
            if (start + j < end) {
                int c = __ldg(all_codes + start + j);
                float4 r = __ldg(emb4 + (size_t)c * D_VEC + t);
                acc.x += r.x; acc.y += r.y; acc.z += r.z; acc.w += r.w;
            }
        }

        // sinusoidal time embedding: cat(sin(t*ts), cos(t*ts))
        float tm = __ldg(times + v);
        tm = fminf(fmaxf(tm, 0.0f), MAX_DAYS_M1);

        int d0 = t * 4;
        float4 te;
        if (d0 < D_DIM / 2) {
            float a0 = tm * __ldg(timescales + d0 + 0);
            float a1 = tm * __ldg(timescales + d0 + 1);
            float a2 = tm * __ldg(timescales + d0 + 2);
            float a3 = tm * __ldg(timescales + d0 + 3);
            te.x = sinf(a0); te.y = sinf(a1); te.z = sinf(a2); te.w = sinf(a3);
        } else {
            int dh = d0 - D_DIM / 2;
            float a0 = tm * __ldg(timescales + dh + 0);
            float a1 = tm * __ldg(timescales + dh + 1);
            float a2 = tm * __ldg(timescales + dh + 2);
            float a3 = tm * __ldg(timescales + dh + 3);
            te.x = cosf(a0); te.y = cosf(a1); te.z = cosf(a2); te.w = cosf(a3);
        }

        acc.x += te.x; acc.y += te.y; acc.z += te.z; acc.w += te.w;
        out4[(size_t)row * D_VEC + t] = acc;
    }
}

extern "C" void kernel_launch(void* const* d_in, const int* in_sizes, int n_in,
                              void* d_out, int out_size) {
    const int*   all_codes     = (const int*)d_in[0];
    const int*   code_to_visit = (const int*)d_in[1];
    const int*   visit_person  = (const int*)d_in[2];
    const int*   visit_slot    = (const int*)d_in[3];
    const float* times         = (const float*)d_in[4];
    const float* concept_emb   = (const float*)d_in[5];
    const float* pad_embedding = (const float*)d_in[6];
    const float* timescales    = (const float*)d_in[7];
    float* out = (float*)d_out;

    int total_codes  = in_sizes[0];
    int total_visits = in_sizes[2];
    int n_rows = out_size / D_DIM;   // B * MAX_VISITS

    int build_items = (total_codes + 3) / 4;
    if (build_items < total_visits) build_items = total_visits;
    vt_build_kernel<<<(build_items + 255) / 256, 256>>>(
        code_to_visit, visit_person, visit_slot, total_codes, total_visits);

    // Persistent grid: 4 blocks per SM (occupancy-limited anyway), grid-stride.
    int n_blocks = 148 * 4;
    int max_blocks = (n_rows + ROWS_PER_ITER - 1) / ROWS_PER_ITER;
    if (n_blocks > max_blocks) n_blocks = max_blocks;
    vt_main_kernel<<<n_blocks, 64 * ROWS_PER_ITER>>>(
        all_codes, times, concept_emb, pad_embedding, timescales, out, n_rows);
}

// round 5
// speedup vs baseline: 1.0381x; 1.0381x over previous
#include <cuda_runtime.h>
#include <cuda_bf16.h>
#include <math.h>

// Problem constants (fixed by the dataset)
#define MAX_VISITS   510
#define B_CAP        128
#define TOTAL_VISITS_CAP 38400
#define D_DIM        256
#define D_VEC        (D_DIM / 4)   // 64 float4 per row
#define MAX_DAYS_M1  364.0f

// Scratch (allocation-free rule: __device__ globals).
// Zero-initialized at module load. slot_map encodes v+1; 0 = pad row.
// Pad entries are never written (constant 0); visit entries are rewritten
// with identical values every call, so work/output are call-invariant.
__device__ int g_slot_map[B_CAP * MAX_VISITS];
__device__ int g_seg_start[TOTAL_VISITS_CAP];
__device__ int g_seg_end[TOTAL_VISITS_CAP];

// One thread handles 4 consecutive code_to_visit entries (int4) and detects
// segment boundaries; every visit has >=1 code so both bounds are always
// fully rewritten each call. Also scatters the visit->row map.
__global__ void vt_build_kernel(const int* __restrict__ code_to_visit,
                                const int* __restrict__ visit_person,
                                const int* __restrict__ visit_slot,
                                int total_codes, int total_visits) {
    int i = blockIdx.x * blockDim.x + threadIdx.x;
    int base = i * 4;
    if (base + 4 <= total_codes) {
        int4 c = *reinterpret_cast<const int4*>(code_to_visit + base);
        if (base == 0) g_seg_start[c.x] = 0;
        if (c.x != c.y) { g_seg_end[c.x] = base + 1; g_seg_start[c.y] = base + 1; }
        if (c.y != c.z) { g_seg_end[c.y] = base + 2; g_seg_start[c.z] = base + 2; }
        if (c.z != c.w) { g_seg_end[c.z] = base + 3; g_seg_start[c.w] = base + 3; }
        if (base + 4 == total_codes) {
            g_seg_end[c.w] = total_codes;
        } else {
            int nxt = code_to_visit[base + 4];
            if (c.w != nxt) { g_seg_end[c.w] = base + 4; g_seg_start[nxt] = base + 4; }
        }
    } else if (base < total_codes) {
        for (int k = base; k < total_codes; ++k) {
            int v = code_to_visit[k];
            if (k == 0 || code_to_visit[k - 1] != v) g_seg_start[v] = k;
            if (k == total_codes - 1 || code_to_visit[k + 1] != v) g_seg_end[v] = k + 1;
        }
    }
    if (i < total_visits) {
        g_slot_map[visit_person[i] * MAX_VISITS + visit_slot[i]] = i + 1;
    }
}

// R2-winning structure: 128-thread block handles 2 rows; 64 threads per row,
// one float4 (4 consecutive dims) each. Fixed predicated unroll-16 gather
// keeps 16 independent LDG.128 in flight per thread (MLP=16).
// New vs R2: the 16 code indices (+ the visit time) are staged into smem
// ONCE per row by one warp, so the gather loop reads indices via broadcast
// LDS instead of each warp redundantly issuing 16 uniform LDGs.
// Trig uses __sinf/__cosf (args <= 364 rad; fast-path reduction error ~2e-5,
// far below the 1e-3 tolerance).
__global__ __launch_bounds__(128) void vt_main_kernel(
    const float* __restrict__ all_times_unused,  // keep signature simple
    const int* __restrict__ all_codes,
    const float* __restrict__ times,
    const float* __restrict__ concept_emb,
    const float* __restrict__ pad_embedding,
    const float* __restrict__ timescales,
    float* __restrict__ out,
    int n_rows) {
    __shared__ int   s_idx[2][16];
    __shared__ float s_time[2];

    int tid  = threadIdx.x;          // 0..127
    int sub  = tid >> 6;             // which of the block's 2 rows
    int t    = tid & 63;             // lane within row
    int wid  = tid >> 5;             // warp 0..3
    int lane = tid & 31;
    int row  = blockIdx.x * 2 + sub;
    bool live = (row < n_rows);

    int ve = live ? g_slot_map[row] : 0;

    // Stage indices + time: warp 0 stages row 0, warp 2 stages row 1.
    if ((wid & 1) == 0 && ve != 0) {
        int v = ve - 1;
        if (lane == 0) s_time[sub] = __ldg(times + v);
        int start = g_seg_start[v];
        int end   = g_seg_end[v];
        if (lane < 16) {
            int p = start + lane;
            s_idx[sub][lane] = (p < end) ? __ldg(all_codes + p) : -1;
        }
    }
    __syncthreads();

    if (!live) return;

    float4* out4 = reinterpret_cast<float4*>(out);
    size_t obase = (size_t)row * D_VEC + t;

    if (ve == 0) {
        out4[obase] = __ldg(reinterpret_cast<const float4*>(pad_embedding) + t);
        return;
    }

    const float4* emb4 = reinterpret_cast<const float4*>(concept_emb);
    float4 acc = make_float4(0.f, 0.f, 0.f, 0.f);

    #pragma unroll
    for (int j = 0; j < 16; ++j) {
        int c = s_idx[sub][j];
        if (c >= 0) {
            float4 r = __ldg(emb4 + (size_t)c * D_VEC + t);
            acc.x += r.x; acc.y += r.y; acc.z += r.z; acc.w += r.w;
        }
    }

    // Sinusoidal time embedding: out[d] += sin(t*ts[d]) (d<128) / cos(t*ts[d-128]).
    // Both halves use the same 4 timescales at index (t & 31).
    float tm = s_time[sub];
    tm = fminf(fmaxf(tm, 0.0f), MAX_DAYS_M1);
    float4 ts = __ldg(reinterpret_cast<const float4*>(timescales) + (t & 31));

    float4 te;
    if (t < 32) {
        te.x = __sinf(tm * ts.x); te.y = __sinf(tm * ts.y);
        te.z = __sinf(tm * ts.z); te.w = __sinf(tm * ts.w);
    } else {
        te.x = __cosf(tm * ts.x); te.y = __cosf(tm * ts.y);
        te.z = __cosf(tm * ts.z); te.w = __cosf(tm * ts.w);
    }

    acc.x += te.x; acc.y += te.y; acc.z += te.z; acc.w += te.w;
    out4[obase] = acc;
}

extern "C" void kernel_launch(void* const* d_in, const int* in_sizes, int n_in,
                              void* d_out, int out_size) {
    const int*   all_codes     = (const int*)d_in[0];
    const int*   code_to_visit = (const int*)d_in[1];
    const int*   visit_person  = (const int*)d_in[2];
    const int*   visit_slot    = (const int*)d_in[3];
    const float* times         = (const float*)d_in[4];
    const float* concept_emb   = (const float*)d_in[5];
    const float* pad_embedding = (const float*)d_in[6];
    const float* timescales    = (const float*)d_in[7];
    float* out = (float*)d_out;

    int total_codes  = in_sizes[0];
    int total_visits = in_sizes[2];
    int n_rows = out_size / D_DIM;   // B * MAX_VISITS

    int build_items = (total_codes + 3) / 4;
    if (build_items < total_visits) build_items = total_visits;
    vt_build_kernel<<<(build_items + 255) / 256, 256>>>(
        code_to_visit, visit_person, visit_slot, total_codes, total_visits);

    vt_main_kernel<<<(n_rows + 1) / 2, 128>>>(
        nullptr, all_codes, times, concept_emb, pad_embedding, timescales,
        out, n_rows);
}

// round 6
// speedup vs baseline: 1.1187x; 1.0776x over previous
#include <cuda_runtime.h>
#include <cuda_bf16.h>
#include <math.h>

// Problem constants (fixed by the dataset)
#define MAX_VISITS   510
#define B_CAP        128
#define TOTAL_VISITS_CAP 38400
#define D_DIM        256
#define D_VEC        (D_DIM / 4)   // 64 float4 per row
#define MAX_DAYS_M1  364.0f

// Scratch (allocation-free rule: __device__ globals).
// Zero-initialized at module load. slot_map encodes v+1; 0 = pad row.
// Pad entries are never written (constant 0); visit entries are rewritten
// with identical values every call, so work/output are call-invariant.
__device__ int g_slot_map[B_CAP * MAX_VISITS];
__device__ int g_seg_start[TOTAL_VISITS_CAP];
__device__ int g_seg_end[TOTAL_VISITS_CAP];

// One thread handles 4 consecutive code_to_visit entries (int4) and detects
// segment boundaries; every visit has >=1 code so both bounds are always
// fully rewritten each call. Also scatters the visit->row map.
__global__ void vt_build_kernel(const int* __restrict__ code_to_visit,
                                const int* __restrict__ visit_person,
                                const int* __restrict__ visit_slot,
                                int total_codes, int total_visits) {
    int i = blockIdx.x * blockDim.x + threadIdx.x;
    int base = i * 4;
    if (base + 4 <= total_codes) {
        int4 c = *reinterpret_cast<const int4*>(code_to_visit + base);
        if (base == 0) g_seg_start[c.x] = 0;
        if (c.x != c.y) { g_seg_end[c.x] = base + 1; g_seg_start[c.y] = base + 1; }
        if (c.y != c.z) { g_seg_end[c.y] = base + 2; g_seg_start[c.z] = base + 2; }
        if (c.z != c.w) { g_seg_end[c.z] = base + 3; g_seg_start[c.w] = base + 3; }
        if (base + 4 == total_codes) {
            g_seg_end[c.w] = total_codes;
        } else {
            int nxt = code_to_visit[base + 4];
            if (c.w != nxt) { g_seg_end[c.w] = base + 4; g_seg_start[nxt] = base + 4; }
        }
    } else if (base < total_codes) {
        for (int k = base; k < total_codes; ++k) {
            int v = code_to_visit[k];
            if (k == 0 || code_to_visit[k - 1] != v) g_seg_start[v] = k;
            if (k == total_codes - 1 || code_to_visit[k + 1] != v) g_seg_end[v] = k + 1;
        }
    }
    if (i < total_visits) {
        g_slot_map[visit_person[i] * MAX_VISITS + visit_slot[i]] = i + 1;
    }
}

// R2-winning body, unchanged: 128-thread block handles 2 rows; 64 threads
// per row, one float4 (4 consecutive dims) each. Per-thread predicated
// unroll-16 gather keeps 16 independent LDG.128 in flight (MLP=16) with no
// barrier / shuffle / staging in front of it — measured best by >3us over
// every alternative.
// Tail only is cheapened: one float4 timescale load at (t & 31) (sin and cos
// halves use identical timescales) and __sinf/__cosf (RRO+MUFU) instead of
// precise polynomials. args <= 364 rad -> error ~2e-5 << 1e-3 tolerance.
__global__ __launch_bounds__(128) void vt_main_kernel(
    const int* __restrict__ all_codes,
    const float* __restrict__ times,
    const float* __restrict__ concept_emb,
    const float* __restrict__ pad_embedding,
    const float* __restrict__ timescales,
    float* __restrict__ out,
    int n_rows) {
    int tid = threadIdx.x;                       // 0..127
    int row = blockIdx.x * 2 + (tid >> 6);       // 2 rows per block
    int t   = tid & 63;                          // lane within row: 0..63
    if (row >= n_rows) return;

    float4* out4 = reinterpret_cast<float4*>(out);

    int ve = g_slot_map[row];
    if (ve == 0) {
        // pad row
        float4 p = __ldg(reinterpret_cast<const float4*>(pad_embedding) + t);
        out4[(size_t)row * D_VEC + t] = p;
        return;
    }
    int v = ve - 1;

    int start = g_seg_start[v];
    int end   = g_seg_end[v];

    const float4* emb4 = reinterpret_cast<const float4*>(concept_emb);
    float4 acc = make_float4(0.f, 0.f, 0.f, 0.f);

    // <=16 codes per visit; fully unrolled predicated loop keeps all index
    // loads and data loads independent -> deep MLP into L2.
    #pragma unroll
    for (int j = 0; j < 16; ++j) {
        if (start + j < end) {
            int c = __ldg(all_codes + start + j);
            float4 r = __ldg(emb4 + (size_t)c * D_VEC + t);
            acc.x += r.x; acc.y += r.y; acc.z += r.z; acc.w += r.w;
        }
    }

    // Sinusoidal time embedding: out[d] += sin(t*ts[d]) (d<128) / cos(t*ts[d-128]).
    float tm = __ldg(times + v);
    tm = fminf(fmaxf(tm, 0.0f), MAX_DAYS_M1);
    float4 ts = __ldg(reinterpret_cast<const float4*>(timescales) + (t & 31));

    float4 te;
    if (t < 32) {
        te.x = __sinf(tm * ts.x); te.y = __sinf(tm * ts.y);
        te.z = __sinf(tm * ts.z); te.w = __sinf(tm * ts.w);
    } else {
        te.x = __cosf(tm * ts.x); te.y = __cosf(tm * ts.y);
        te.z = __cosf(tm * ts.z); te.w = __cosf(tm * ts.w);
    }

    acc.x += te.x; acc.y += te.y; acc.z += te.z; acc.w += te.w;
    out4[(size_t)row * D_VEC + t] = acc;
}

extern "C" void kernel_launch(void* const* d_in, const int* in_sizes, int n_in,
                              void* d_out, int out_size) {
    const int*   all_codes     = (const int*)d_in[0];
    const int*   code_to_visit = (const int*)d_in[1];
    const int*   visit_person  = (const int*)d_in[2];
    const int*   visit_slot    = (const int*)d_in[3];
    const float* times         = (const float*)d_in[4];
    const float* concept_emb   = (const float*)d_in[5];
    const float* pad_embedding = (const float*)d_in[6];
    const float* timescales    = (const float*)d_in[7];
    float* out = (float*)d_out;

    int total_codes  = in_sizes[0];
    int total_visits = in_sizes[2];
    int n_rows = out_size / D_DIM;   // B * MAX_VISITS

    int build_items = (total_codes + 3) / 4;
    if (build_items < total_visits) build_items = total_visits;
    vt_build_kernel<<<(build_items + 255) / 256, 256>>>(
        code_to_visit, visit_person, visit_slot, total_codes, total_visits);

    vt_main_kernel<<<(n_rows + 1) / 2, 128>>>(
        all_codes, times, concept_emb, pad_embedding, timescales, out, n_rows);
}

// round 7
// speedup vs baseline: 1.2842x; 1.1480x over previous
#include <cuda_runtime.h>
#include <cuda_bf16.h>
#include <math.h>

// Problem constants (fixed by the dataset)
#define MAX_VISITS   510
#define B_CAP        128
#define TOTAL_VISITS_CAP 38400
#define D_DIM        256
#define D_VEC        (D_DIM / 4)   // 64 float4 per row
#define MAX_DAYS_M1  364.0f

// Scratch (allocation-free rule: __device__ globals).
// Zero-initialized at module load. slot_map encodes v+1; 0 = pad row.
// Pad entries are never written (constant 0); visit entries are rewritten
// with identical values every call, so work/output are call-invariant.
__device__ int g_slot_map[B_CAP * MAX_VISITS];
__device__ int g_seg_start[TOTAL_VISITS_CAP];
__device__ int g_seg_end[TOTAL_VISITS_CAP];

// One thread handles 4 consecutive code_to_visit entries (int4) and detects
// segment boundaries; every visit has >=1 code so both bounds are always
// fully rewritten each call. Also scatters the visit->row map.
__global__ void vt_build_kernel(const int* __restrict__ code_to_visit,
                                const int* __restrict__ visit_person,
                                const int* __restrict__ visit_slot,
                                int total_codes, int total_visits) {
    int i = blockIdx.x * blockDim.x + threadIdx.x;
    int base = i * 4;
    if (base + 4 <= total_codes) {
        int4 c = *reinterpret_cast<const int4*>(code_to_visit + base);
        if (base == 0) g_seg_start[c.x] = 0;
        if (c.x != c.y) { g_seg_end[c.x] = base + 1; g_seg_start[c.y] = base + 1; }
        if (c.y != c.z) { g_seg_end[c.y] = base + 2; g_seg_start[c.z] = base + 2; }
        if (c.z != c.w) { g_seg_end[c.z] = base + 3; g_seg_start[c.w] = base + 3; }
        if (base + 4 == total_codes) {
            g_seg_end[c.w] = total_codes;
        } else {
            int nxt = code_to_visit[base + 4];
            if (c.w != nxt) { g_seg_end[c.w] = base + 4; g_seg_start[nxt] = base + 4; }
        }
    } else if (base < total_codes) {
        for (int k = base; k < total_codes; ++k) {
            int v = code_to_visit[k];
            if (k == 0 || code_to_visit[k - 1] != v) g_seg_start[v] = k;
            if (k == total_codes - 1 || code_to_visit[k + 1] != v) g_seg_end[v] = k + 1;
        }
    }
    if (i < total_visits) {
        g_slot_map[visit_person[i] * MAX_VISITS + visit_slot[i]] = i + 1;
    }
}

// R2-winning body: 128-thread block handles 2 rows; 64 threads per row, one
// float4 (4 consecutive dims) each. Per-thread predicated unroll-16 gather
// keeps 16 independent LDG.128 in flight (MLP=16), nothing in front of it.
//
// CRITICAL: __launch_bounds__(128, 16) pins the kernel to <=32 regs so the
// full 64-warp occupancy is reachable (32 regs * 64 warps * 32 lanes = whole
// 64K RF). Every regression this session traced to crossing that cliff
// (34+ regs -> 48-warp ceiling -> occ 65% -> +4us).
//
// Tail: scalar timescale loads (register-friendly, as in the 32-reg R2) and
// __sinf/__cosf (RRO+MUFU). args <= 364 rad -> error ~2e-5 << 1e-3 tol.
__global__ __launch_bounds__(128, 16) void vt_main_kernel(
    const int* __restrict__ all_codes,
    const float* __restrict__ times,
    const float* __restrict__ concept_emb,
    const float* __restrict__ pad_embedding,
    const float* __restrict__ timescales,
    float* __restrict__ out,
    int n_rows) {
    int tid = threadIdx.x;                       // 0..127
    int row = blockIdx.x * 2 + (tid >> 6);       // 2 rows per block
    int t   = tid & 63;                          // lane within row: 0..63
    if (row >= n_rows) return;

    float4* out4 = reinterpret_cast<float4*>(out);

    int ve = g_slot_map[row];
    if (ve == 0) {
        // pad row
        float4 p = __ldg(reinterpret_cast<const float4*>(pad_embedding) + t);
        out4[(size_t)row * D_VEC + t] = p;
        return;
    }
    int v = ve - 1;

    int start = g_seg_start[v];
    int end   = g_seg_end[v];

    const float4* emb4 = reinterpret_cast<const float4*>(concept_emb);
    float4 acc = make_float4(0.f, 0.f, 0.f, 0.f);

    // <=16 codes per visit; fully unrolled predicated loop keeps all index
    // loads and data loads independent -> deep MLP into L2.
    #pragma unroll
    for (int j = 0; j < 16; ++j) {
        if (start + j < end) {
            int c = __ldg(all_codes + start + j);
            float4 r = __ldg(emb4 + (size_t)c * D_VEC + t);
            acc.x += r.x; acc.y += r.y; acc.z += r.z; acc.w += r.w;
        }
    }

    // Sinusoidal time embedding: out[d] += sin(t*ts[d]) (d<128) / cos(t*ts[d-128]).
    float tm = __ldg(times + v);
    tm = fminf(fmaxf(tm, 0.0f), MAX_DAYS_M1);

    int d0 = t * 4;
    float4 te;
    if (d0 < D_DIM / 2) {
        float a0 = tm * __ldg(timescales + d0 + 0);
        float a1 = tm * __ldg(timescales + d0 + 1);
        float a2 = tm * __ldg(timescales + d0 + 2);
        float a3 = tm * __ldg(timescales + d0 + 3);
        te.x = __sinf(a0); te.y = __sinf(a1); te.z = __sinf(a2); te.w = __sinf(a3);
    } else {
        int dh = d0 - D_DIM / 2;
        float a0 = tm * __ldg(timescales + dh + 0);
        float a1 = tm * __ldg(timescales + dh + 1);
        float a2 = tm * __ldg(timescales + dh + 2);
        float a3 = tm * __ldg(timescales + dh + 3);
        te.x = __cosf(a0); te.y = __cosf(a1); te.z = __cosf(a2); te.w = __cosf(a3);
    }

    acc.x += te.x; acc.y += te.y; acc.z += te.z; acc.w += te.w;
    out4[(size_t)row * D_VEC + t] = acc;
}

extern "C" void kernel_launch(void* const* d_in, const int* in_sizes, int n_in,
                              void* d_out, int out_size) {
    const int*   all_codes     = (const int*)d_in[0];
    const int*   code_to_visit = (const int*)d_in[1];
    const int*   visit_person  = (const int*)d_in[2];
    const int*   visit_slot    = (const int*)d_in[3];
    const float* times         = (const float*)d_in[4];
    const float* concept_emb   = (const float*)d_in[5];
    const float* pad_embedding = (const float*)d_in[6];
    const float* timescales    = (const float*)d_in[7];
    float* out = (float*)d_out;

    int total_codes  = in_sizes[0];
    int total_visits = in_sizes[2];
    int n_rows = out_size / D_DIM;   // B * MAX_VISITS

    int build_items = (total_codes + 3) / 4;
    if (build_items < total_visits) build_items = total_visits;
    vt_build_kernel<<<(build_items + 255) / 256, 256>>>(
        code_to_visit, visit_person, visit_slot, total_codes, total_visits);

    vt_main_kernel<<<(n_rows + 1) / 2, 128>>>(
        all_codes, times, concept_emb, pad_embedding, timescales, out, n_rows);
}